// round 15
// baseline (speedup 1.0000x reference)
#include <cuda_runtime.h>
#include <cuda_fp16.h>
#include <math.h>
#include <cstdint>

// Problem constants
#define Bn  8
#define Nn  1025
#define Cn  1024
#define Hn  16
#define Mn  (Bn * Nn)    // 8200 true rows
#define PadN 1040        // padded per-batch stride (65 * 16)
#define Mp  (Bn * PadN)  // 8320 = 65 * 128
#define NT  17           // kv tiles of 64
#define NT2 9            // kv pipeline stages of 128
#define SCL 0.1803368801111204f   // 0.125 * log2(e)
#define ONES2 0x3C003C00u         // half2(1.0, 1.0)

// ---------------------------------------------------------------------------
// fp16 fragment-grouped images (same as R13/R14; see earlier notes).
// ---------------------------------------------------------------------------
__device__ __align__(128) uint32_t x_img [(size_t)65 * 16 * 4096];
__device__ __align__(128) uint32_t wq_img[(size_t)24 * 16 * 4096];
__device__ __align__(128) uint32_t wp_img[(size_t)8  * 16 * 4096];
__device__ __align__(128) uint32_t xo_img[(size_t)65 * 16 * 4096];
__device__ __align__(128) uint32_t xn_img[(size_t)65 * 16 * 4096];
__device__ __align__(128) uint32_t q_aimg[(size_t)128 * 33280];   // raw q
__device__ __align__(128) uint32_t k_kimg[(size_t)128 * NT * 2048 + 2048];
__device__ __align__(128) uint32_t v_kimg[(size_t)128 * NT * 2048 + 2048];
__device__ __align__(128) uint32_t v_vimg[(size_t)128 * NT * 2048 + 2048];

// ---------------------------------------------------------------------------
// Helpers
// ---------------------------------------------------------------------------
__device__ __forceinline__ uint32_t smem_u32(const void* p) {
    uint32_t a;
    asm("{ .reg .u64 t; cvta.to.shared.u64 t, %1; cvt.u32.u64 %0, t; }"
        : "=r"(a) : "l"(p));
    return a;
}
__device__ __forceinline__ uint32_t packh2(float lo, float hi) {
    __half2 h = __floats2half2_rn(lo, hi);
    return *reinterpret_cast<uint32_t*>(&h);
}
__device__ __forceinline__ uint32_t pack2h(__half a, __half b) {
    __half2 h = __halves2half2(a, b);
    return *reinterpret_cast<uint32_t*>(&h);
}
__device__ __forceinline__ float ex2f(float x) {
    float r;
    asm("ex2.approx.ftz.f32 %0, %1;" : "=f"(r) : "f"(x));
    return r;
}
__device__ __forceinline__ void lds128(uint4& v, uint32_t a) {
    asm volatile("ld.shared.v4.b32 {%0,%1,%2,%3}, [%4];"
                 : "=r"(v.x), "=r"(v.y), "=r"(v.z), "=r"(v.w) : "r"(a));
}
__device__ __forceinline__ void mma16(float* c, uint32_t a0, uint32_t a1,
                                      uint32_t a2, uint32_t a3,
                                      uint32_t b0, uint32_t b1) {
    asm volatile(
        "mma.sync.aligned.m16n8k16.row.col.f32.f16.f16.f32 "
        "{%0,%1,%2,%3}, {%4,%5,%6,%7}, {%8,%9}, {%0,%1,%2,%3};"
        : "+f"(c[0]), "+f"(c[1]), "+f"(c[2]), "+f"(c[3])
        : "r"(a0), "r"(a1), "r"(a2), "r"(a3), "r"(b0), "r"(b1));
}
#define CP16(dst, src) \
    asm volatile("cp.async.cg.shared.global [%0], [%1], 16;" :: "r"(dst), "l"(src))
#define CP_COMMIT() asm volatile("cp.async.commit_group;")
#define CP_WAIT0()  asm volatile("cp.async.wait_group 0;" ::: "memory")
#define CP_WAIT1()  asm volatile("cp.async.wait_group 1;" ::: "memory")

__device__ __forceinline__ uint4 cfrag_pack(const float* lo, const float* hi) {
    uint4 u;
    u.x = packh2(lo[0], lo[1]);
    u.y = packh2(lo[2], lo[3]);
    u.z = packh2(hi[0], hi[1]);
    u.w = packh2(hi[2], hi[3]);
    return u;
}

// ---------------------------------------------------------------------------
// perm16: fp32 row-major -> fp16 GEMM images, 16-row band per block.
// ---------------------------------------------------------------------------
#define XB  (Mp / 16)        // 520
#define WQB (3072 / 16)      // 192
#define WPB (1024 / 16)      // 64

__global__ void __launch_bounds__(256)
perm16(const float* __restrict__ x, const float* __restrict__ wq,
       const float* __restrict__ wp, uint32_t* __restrict__ xi,
       uint32_t* __restrict__ wqi, uint32_t* __restrict__ wpi)
{
    __shared__ __half s[16][1032];
    const int bid = blockIdx.x;
    const int tid = threadIdx.x;

    const float* src;
    uint32_t* dst;
    int band, rbase;
    bool padded;
    if (bid < XB) {
        band = bid; src = x; dst = xi; padded = true; rbase = 0;
    } else if (bid < XB + WQB) {
        band = bid - XB; src = wq; dst = wqi; padded = false;
        rbase = band * 16;
    } else {
        band = bid - XB - WQB; src = wp; dst = wpi; padded = false;
        rbase = band * 16;
    }

#pragma unroll
    for (int e = 0; e < 32; e++) {
        const int idx = tid + e * 256;
        const int r16 = idx >> 9;
        const int kk = idx & 511;
        float2 v = make_float2(0.f, 0.f);
        if (padded) {
            const int row = band * 16 + r16;
            const int b = row / PadN, n = row - b * PadN;
            if (n < Nn)
                v = *(const float2*)(src + ((size_t)b * Nn + n) * Cn + 2 * kk);
        } else {
            v = *(const float2*)(src + (size_t)(rbase + r16) * Cn + 2 * kk);
        }
        *(__half2*)&s[r16][2 * kk] = __floats2half2_rn(v.x, v.y);
    }
    __syncthreads();

    const int mt = band >> 3, R = band & 7;
#pragma unroll
    for (int e = 0; e < 8; e++) {
        const int f = tid + e * 256;
        const int kc = f >> 7, c8 = (f >> 5) & 3, lane = f & 31;
        const int g2 = lane >> 2, q2 = lane & 3;
        const int col = kc * 64 + c8 * 16 + 2 * q2;
        uint4 u;
        u.x = *(const uint32_t*)&s[g2][col];
        u.y = *(const uint32_t*)&s[g2 + 8][col];
        u.z = *(const uint32_t*)&s[g2][col + 8];
        u.w = *(const uint32_t*)&s[g2 + 8][col + 8];
        *(uint4*)(dst + (size_t)(mt * 16 + kc) * 4096 +
                  ((R * 4 + c8) * 32 + lane) * 4) = u;
    }
}

// ---------------------------------------------------------------------------
// fp16 GEMM (R13 config + y0 tile offset for the split-half launches).
// ---------------------------------------------------------------------------
template <int MODE>
__global__ void __launch_bounds__(256, 2)
gemm_h(const uint32_t* __restrict__ A0img, const uint32_t* __restrict__ A1img,
       const uint32_t* __restrict__ Bimg, const float* __restrict__ bias,
       float* __restrict__ Cout, int y0)
{
    extern __shared__ char smraw[];
    const uint32_t sb = smem_u32(smraw);
    const int tid = threadIdx.x;
    const int w = tid >> 5, l = tid & 31;
    const int q = l & 3, g = l >> 2;
    const int yt = blockIdx.y + y0;
    const int m0 = yt * 128;
    const int n0 = blockIdx.x * 128;
    const int R0  = (w & 3) * 2;
    const int wn2 = w >> 2;

    const uint32_t* Aimg = blockIdx.z ? A1img : A0img;
    if (MODE == 1) Cout += (size_t)blockIdx.z * Mn * Cn;

    const char* Ab = (const char*)(Aimg + (size_t)yt * 16 * 4096);
    const char* Bb = (const char*)(Bimg + (size_t)blockIdx.x * 16 * 4096);

#define GISSUE(kt) do {                                                      \
    const uint32_t st = sb + (uint32_t)((kt) % 3) * 32768u;                  \
    const char* as = Ab + (size_t)(kt) * 16384;                              \
    const char* bs = Bb + (size_t)(kt) * 16384;                              \
    _Pragma("unroll")                                                        \
    for (int i_ = 0; i_ < 4; i_++) {                                         \
        CP16(st + (tid + i_ * 256) * 16,          as + (tid + i_ * 256) * 16); \
        CP16(st + 16384u + (tid + i_ * 256) * 16, bs + (tid + i_ * 256) * 16); \
    }                                                                        \
    CP_COMMIT(); } while (0)

    float acc[2][8][4];
#pragma unroll
    for (int i = 0; i < 2; i++)
#pragma unroll
        for (int j = 0; j < 8; j++)
#pragma unroll
            for (int e = 0; e < 4; e++) acc[i][j][e] = 0.f;

    GISSUE(0);
    GISSUE(1);

    for (int kt = 0; kt < 16; kt++) {
        if (kt < 15) { CP_WAIT1(); } else { CP_WAIT0(); }
        __syncthreads();
        const uint32_t ab = sb + (uint32_t)(kt % 3) * 32768u;
        const uint32_t bb = ab + 16384u;
#pragma unroll
        for (int c8 = 0; c8 < 4; c8++) {
            uint4 af[2], bf[4];
#pragma unroll
            for (int i = 0; i < 2; i++)
                lds128(af[i], ab + (((R0 + i) * 4 + c8) * 32 + l) * 16);
#pragma unroll
            for (int nn = 0; nn < 4; nn++)
                lds128(bf[nn], bb + (((wn2 * 4 + nn) * 4 + c8) * 32 + l) * 16);
#pragma unroll
            for (int i = 0; i < 2; i++)
#pragma unroll
                for (int nn = 0; nn < 4; nn++) {
                    mma16(acc[i][2 * nn],     af[i].x, af[i].y, af[i].z, af[i].w,
                          bf[nn].x, bf[nn].z);
                    mma16(acc[i][2 * nn + 1], af[i].x, af[i].y, af[i].z, af[i].w,
                          bf[nn].y, bf[nn].w);
                }
        }
        if (kt + 2 < 16) GISSUE(kt + 2);
    }
#undef GISSUE

    if (MODE == 0) {
        const int gn_base = n0 + wn2 * 64;
        const int sel = gn_base >> 10;
        const int h   = (gn_base & 1023) >> 6;
        __half* stg = (__half*)(smraw + 32768 + w * 2176);
#pragma unroll
        for (int i = 0; i < 2; i++) {
            const int gmb = m0 + (R0 + i) * 16;
            const int b   = gmb / PadN;
            const int tok = gmb - b * PadN;
            const int bh  = b * Hn + h;
            const int nb16 = tok >> 4;
            const int t    = tok >> 6;
            const int N16  = (tok & 63) >> 4;
            uint32_t* aimg_p = q_aimg + (size_t)bh * 33280;
            uint32_t* kimg_p = ((sel == 1) ? k_kimg : v_kimg) +
                               ((size_t)bh * NT + t) * 2048;
#pragma unroll
            for (int c8 = 0; c8 < 4; c8++) {
                const float* lo = acc[i][2 * c8];
                const float* hi = acc[i][2 * c8 + 1];
                if (sel == 0)
                    *(uint4*)(aimg_p + ((nb16 * 4 + c8) * 32 + l) * 4) =
                        cfrag_pack(lo, hi);
                else
                    *(uint4*)(kimg_p + ((N16 * 4 + c8) * 32 + l) * 4) =
                        cfrag_pack(lo, hi);
            }
            if (sel == 2) {
#pragma unroll
                for (int j = 0; j < 8; j++) {
                    *(__half2*)(stg + g * 66 + 8 * j + 2 * q) =
                        __floats2half2_rn(acc[i][j][0], acc[i][j][1]);
                    *(__half2*)(stg + (g + 8) * 66 + 8 * j + 2 * q) =
                        __floats2half2_rn(acc[i][j][2], acc[i][j][3]);
                }
                __syncwarp();
                uint32_t* vvp = v_vimg + ((size_t)bh * NT + t) * 2048;
#pragma unroll
                for (int b2 = 0; b2 < 4; b2++) {
                    const int d0 = b2 * 16 + g, d1 = d0 + 8;
                    const int kA = 2 * q, kB = 2 * q + 8;
                    uint4 u;
                    u.x = pack2h(stg[kA * 66 + d0], stg[(kA + 1) * 66 + d0]);
                    u.y = pack2h(stg[kA * 66 + d1], stg[(kA + 1) * 66 + d1]);
                    u.z = pack2h(stg[kB * 66 + d0], stg[(kB + 1) * 66 + d0]);
                    u.w = pack2h(stg[kB * 66 + d1], stg[(kB + 1) * 66 + d1]);
                    *(uint4*)(vvp + ((b2 * 4 + N16) * 32 + l) * 4) = u;
                }
                __syncwarp();
            }
        }
    } else {
#pragma unroll
        for (int i = 0; i < 2; i++) {
            const int gmb = m0 + (R0 + i) * 16;
            const int b   = gmb / PadN;
            const int tok0 = gmb - b * PadN + g;
            const int tok1 = tok0 + 8;
            float* r0 = Cout + ((size_t)b * Nn + tok0) * Cn;
            float* r1 = Cout + ((size_t)b * Nn + tok1) * Cn;
            const bool v0 = tok0 < Nn, v1 = tok1 < Nn;
#pragma unroll
            for (int j = 0; j < 8; j++) {
                const int gn = n0 + wn2 * 64 + 8 * j + 2 * q;
                float2 bv = *(const float2*)(bias + gn);
                if (v0)
                    *(float2*)(r0 + gn) = make_float2(acc[i][j][0] + bv.x,
                                                      acc[i][j][1] + bv.y);
                if (v1)
                    *(float2*)(r1 + gn) = make_float2(acc[i][j][2] + bv.x,
                                                      acc[i][j][3] + bv.y);
            }
        }
    }
}

// ---------------------------------------------------------------------------
// Fused fp16 flash attention (R14 + l-sum via ones-MMA: no FADD chain, no
// final shfl reduction — MMA reduces across k internally, so lacc[0]/lacc[2]
// are complete row sums of the exact fp16 P used by PV).
// ---------------------------------------------------------------------------
__global__ void __launch_bounds__(256, 2)
attn_h(const uint32_t* __restrict__ Qa, const uint32_t* __restrict__ Kk0,
       const uint32_t* __restrict__ Kk1, const uint32_t* __restrict__ Vv,
       uint32_t* __restrict__ X0, uint32_t* __restrict__ X1, int bh0)
{
    extern __shared__ char smraw[];
    const uint32_t sb = smem_u32(smraw);
    const int tid = threadIdx.x;
    const int w = tid >> 5, l = tid & 31;
    const int bh = blockIdx.y + bh0;
    const int b = bh >> 4, h = bh & 15;
    const int z = blockIdx.z;
    const int gr_base = blockIdx.x * 128 + w * 16;
    const int nb  = blockIdx.x * 8 + w;
    const bool act = (gr_base < Nn);
    const float off  = z ? 14.0f : 0.0f;
    const float corr = z ? (63.0f / 16384.0f) : 63.0f;   // 63 * 2^-off

    const uint32_t* Kk = z ? Kk1 : Kk0;
    uint32_t*       Xi = z ? X1 : X0;

    const char* Kb = (const char*)(Kk + (size_t)bh * NT * 2048);
    const char* Vb = (const char*)(Vv + (size_t)bh * NT * 2048);

    uint4 qa[4];
    if (act) {
        const uint32_t* qp;
        int blk4;
        if (z == 0) { qp = Qa + (size_t)bh * 33280;                 blk4 = nb * 4; }
        else        { qp = Kk1 + ((size_t)bh * NT + (nb >> 2)) * 2048;
                      blk4 = (nb & 3) * 4; }
#pragma unroll
        for (int c8 = 0; c8 < 4; c8++)
            qa[c8] = *(const uint4*)(qp + ((blk4 + c8) * 32 + l) * 4);
    } else {
#pragma unroll
        for (int c8 = 0; c8 < 4; c8++) qa[c8] = make_uint4(0, 0, 0, 0);
    }

    float o[8][4];
#pragma unroll
    for (int j = 0; j < 8; j++)
#pragma unroll
        for (int e = 0; e < 4; e++) o[j][e] = 0.f;
    float lacc[4] = {0.f, 0.f, 0.f, 0.f};   // row sums via ones-MMA

#define AISSUE(T) do {                                                       \
    const uint32_t bo = sb + (uint32_t)((T) % 3) * 32768u;                   \
    const char* ks = Kb + (size_t)(T) * 16384;                               \
    const char* vs = Vb + (size_t)(T) * 16384;                               \
    _Pragma("unroll")                                                        \
    for (int i_ = 0; i_ < 4; i_++) {                                         \
        CP16(bo + (tid + i_ * 256) * 16,          ks + (tid + i_ * 256) * 16); \
        CP16(bo + 16384u + (tid + i_ * 256) * 16, vs + (tid + i_ * 256) * 16); \
    }                                                                        \
    CP_COMMIT(); } while (0)

    AISSUE(0);
    AISSUE(1);

    for (int T = 0; T < NT2; T++) {
        if (T < NT2 - 1) { CP_WAIT1(); } else { CP_WAIT0(); }
        __syncthreads();
        const uint32_t stg0 = sb + (uint32_t)(T % 3) * 32768u;

#pragma unroll
        for (int sub = 0; sub < 2; sub++) {
            const int kvbase = T * 128 + sub * 64;
            if (!act || kvbase >= Nn) continue;
            const uint32_t k_s = stg0 + (uint32_t)sub * 8192u;
            const uint32_t v_s = stg0 + 16384u + (uint32_t)sub * 8192u;

            // S = Q K^T  (raw, 16 x 64 per warp)
            float sa[8][4];
#pragma unroll
            for (int j = 0; j < 8; j++)
#pragma unroll
                for (int e = 0; e < 4; e++) sa[j][e] = 0.f;
#pragma unroll
            for (int c8 = 0; c8 < 4; c8++) {
#pragma unroll
                for (int n16 = 0; n16 < 4; n16++) {
                    uint4 bf;
                    lds128(bf, k_s + ((n16 * 4 + c8) * 32 + l) * 16);
                    mma16(sa[2 * n16],     qa[c8].x, qa[c8].y, qa[c8].z,
                          qa[c8].w, bf.x, bf.z);
                    mma16(sa[2 * n16 + 1], qa[c8].x, qa[c8].y, qa[c8].z,
                          qa[c8].w, bf.y, bf.w);
                }
            }

            // P = 2^(s*SCL - off) packed to fp16 A-frags; row sums via
            // ones-MMA (l accumulated on the tensor pipe, fp32)
#pragma unroll
            for (int c = 0; c < 4; c++) {
                const uint32_t a0 = packh2(ex2f(sa[2 * c][0] * SCL - off),
                                           ex2f(sa[2 * c][1] * SCL - off));
                const uint32_t a1 = packh2(ex2f(sa[2 * c][2] * SCL - off),
                                           ex2f(sa[2 * c][3] * SCL - off));
                const uint32_t a2 = packh2(ex2f(sa[2 * c + 1][0] * SCL - off),
                                           ex2f(sa[2 * c + 1][1] * SCL - off));
                const uint32_t a3 = packh2(ex2f(sa[2 * c + 1][2] * SCL - off),
                                           ex2f(sa[2 * c + 1][3] * SCL - off));
                mma16(lacc, a0, a1, a2, a3, ONES2, ONES2);
#pragma unroll
                for (int n16 = 0; n16 < 4; n16++) {
                    uint4 vf;
                    lds128(vf, v_s + ((n16 * 4 + c) * 32 + l) * 16);
                    mma16(o[2 * n16],     a0, a1, a2, a3, vf.x, vf.z);
                    mma16(o[2 * n16 + 1], a0, a1, a2, a3, vf.y, vf.w);
                }
            }
        }

        if (T + 2 < NT2) AISSUE(T + 2);
    }
#undef AISSUE

    if (act) {
        // lacc[0]/lacc[2] are complete row sums (rows g, g+8);
        // subtract the exact zero-column contribution.
        const float inv0 = 1.0f / (lacc[0] - corr);
        const float inv1 = 1.0f / (lacc[2] - corr);

        const int m_base = b * PadN + gr_base;
        const int mt = m_base >> 7, R = (m_base & 127) >> 4;
        uint32_t* tb = Xi + (size_t)(mt * 16 + h) * 4096;
#pragma unroll
        for (int c8 = 0; c8 < 4; c8++) {
            uint4 u;
            u.x = packh2(o[2 * c8][0] * inv0,     o[2 * c8][1] * inv0);
            u.y = packh2(o[2 * c8][2] * inv1,     o[2 * c8][3] * inv1);
            u.z = packh2(o[2 * c8 + 1][0] * inv0, o[2 * c8 + 1][1] * inv0);
            u.w = packh2(o[2 * c8 + 1][2] * inv1, o[2 * c8 + 1][3] * inv1);
            *(uint4*)(tb + ((R * 4 + c8) * 32 + l) * 4) = u;
        }
    }
}

// ---------------------------------------------------------------------------
// Launch: batch-split fork/join pipeline on two streams (R14 structure).
// ---------------------------------------------------------------------------
extern "C" void kernel_launch(void* const* d_in, const int* in_sizes, int n_in,
                              void* d_out, int out_size)
{
    const float* x      = (const float*)d_in[0];
    const float* w_qkv  = (const float*)d_in[1];
    const float* w_proj = (const float*)d_in[2];
    const float* b_proj = (const float*)d_in[3];
    float*       out    = (float*)d_out;

    uint32_t *xi, *wqi, *wpi, *xoi, *xni, *qai, *kki, *vki, *vvi;
    cudaGetSymbolAddress((void**)&xi,  x_img);
    cudaGetSymbolAddress((void**)&wqi, wq_img);
    cudaGetSymbolAddress((void**)&wpi, wp_img);
    cudaGetSymbolAddress((void**)&xoi, xo_img);
    cudaGetSymbolAddress((void**)&xni, xn_img);
    cudaGetSymbolAddress((void**)&qai, q_aimg);
    cudaGetSymbolAddress((void**)&kki, k_kimg);
    cudaGetSymbolAddress((void**)&vki, v_kimg);
    cudaGetSymbolAddress((void**)&vvi, v_vimg);

    const int smem_gemm = 98304;
    const int smem_attn = 98304;
    cudaFuncSetAttribute(gemm_h<0>, cudaFuncAttributeMaxDynamicSharedMemorySize,
                         smem_gemm);
    cudaFuncSetAttribute(gemm_h<1>, cudaFuncAttributeMaxDynamicSharedMemorySize,
                         smem_gemm);
    cudaFuncSetAttribute(attn_h, cudaFuncAttributeMaxDynamicSharedMemorySize,
                         smem_attn);

    static cudaStream_t s1 = nullptr;
    static cudaEvent_t evPerm, evG0a, evAttnA, evEnd;
    if (s1 == nullptr) {
        cudaStreamCreateWithFlags(&s1, cudaStreamNonBlocking);
        cudaEventCreateWithFlags(&evPerm,  cudaEventDisableTiming);
        cudaEventCreateWithFlags(&evG0a,   cudaEventDisableTiming);
        cudaEventCreateWithFlags(&evAttnA, cudaEventDisableTiming);
        cudaEventCreateWithFlags(&evEnd,   cudaEventDisableTiming);
    }

    // 0) images
    perm16<<<XB + WQB + WPB, 256>>>(x, w_qkv, w_proj, xi, wqi, wpi);
    cudaEventRecord(evPerm, 0);
    cudaStreamWaitEvent(s1, evPerm, 0);

    // 1) QKV projection, split by row tiles
    gemm_h<0><<<dim3(24, 32, 1), 256, smem_gemm, s1>>>(xi, xi, wqi, nullptr,
                                                       nullptr, 33);  // g0b
    gemm_h<0><<<dim3(24, 33, 1), 256, smem_gemm>>>(xi, xi, wqi, nullptr,
                                                   nullptr, 0);       // g0a
    cudaEventRecord(evG0a, 0);
    cudaStreamWaitEvent(s1, evG0a, 0);

    // 2) attention, split by bh (batch)
    attn_h<<<dim3(9, 64, 2), 256, smem_attn>>>(qai, kki, vki, vvi,
                                               xoi, xni, 0);          // attnA
    attn_h<<<dim3(9, 64, 2), 256, smem_attn, s1>>>(qai, kki, vki, vvi,
                                                   xoi, xni, 64);     // attnB
    cudaEventRecord(evAttnA, 0);
    cudaStreamWaitEvent(s1, evAttnA, 0);

    // 3) projections, split by row tiles
    gemm_h<1><<<dim3(8, 32, 2), 256, smem_gemm>>>(xni, xoi, wpi, b_proj,
                                                  out, 0);            // projA
    gemm_h<1><<<dim3(8, 33, 2), 256, smem_gemm, s1>>>(xni, xoi, wpi, b_proj,
                                                      out, 32);       // projB

    // join
    cudaEventRecord(evEnd, s1);
    cudaStreamWaitEvent(0, evEnd, 0);
}

// round 16
// speedup vs baseline: 1.0142x; 1.0142x over previous
#include <cuda_runtime.h>
#include <cuda_fp16.h>
#include <math.h>
#include <cstdint>

// Problem constants
#define Bn  8
#define Nn  1025
#define Cn  1024
#define Hn  16
#define Mn  (Bn * Nn)    // 8200 true rows
#define PadN 1040        // padded per-batch stride (65 * 16)
#define Mp  (Bn * PadN)  // 8320 = 65 * 128
#define NT  17           // kv tiles of 64
#define NT2 9            // kv pipeline stages of 128
#define SCL 0.1803368801111204f   // 0.125 * log2(e)

// ---------------------------------------------------------------------------
// fp16 fragment-grouped images (same as R13/R14; see earlier notes).
// ---------------------------------------------------------------------------
__device__ __align__(128) uint32_t x_img [(size_t)65 * 16 * 4096];
__device__ __align__(128) uint32_t wq_img[(size_t)24 * 16 * 4096];
__device__ __align__(128) uint32_t wp_img[(size_t)8  * 16 * 4096];
__device__ __align__(128) uint32_t xo_img[(size_t)65 * 16 * 4096];
__device__ __align__(128) uint32_t xn_img[(size_t)65 * 16 * 4096];
__device__ __align__(128) uint32_t q_aimg[(size_t)128 * 33280];   // raw q
__device__ __align__(128) uint32_t k_kimg[(size_t)128 * NT * 2048 + 2048];
__device__ __align__(128) uint32_t v_kimg[(size_t)128 * NT * 2048 + 2048];
__device__ __align__(128) uint32_t v_vimg[(size_t)128 * NT * 2048 + 2048];

// ---------------------------------------------------------------------------
// Helpers
// ---------------------------------------------------------------------------
__device__ __forceinline__ uint32_t smem_u32(const void* p) {
    uint32_t a;
    asm("{ .reg .u64 t; cvta.to.shared.u64 t, %1; cvt.u32.u64 %0, t; }"
        : "=r"(a) : "l"(p));
    return a;
}
__device__ __forceinline__ uint32_t packh2(float lo, float hi) {
    __half2 h = __floats2half2_rn(lo, hi);
    return *reinterpret_cast<uint32_t*>(&h);
}
__device__ __forceinline__ uint32_t pack2h(__half a, __half b) {
    __half2 h = __halves2half2(a, b);
    return *reinterpret_cast<uint32_t*>(&h);
}
__device__ __forceinline__ float ex2f(float x) {
    float r;
    asm("ex2.approx.ftz.f32 %0, %1;" : "=f"(r) : "f"(x));
    return r;
}
__device__ __forceinline__ void lds128(uint4& v, uint32_t a) {
    asm volatile("ld.shared.v4.b32 {%0,%1,%2,%3}, [%4];"
                 : "=r"(v.x), "=r"(v.y), "=r"(v.z), "=r"(v.w) : "r"(a));
}
__device__ __forceinline__ void mma16(float* c, uint32_t a0, uint32_t a1,
                                      uint32_t a2, uint32_t a3,
                                      uint32_t b0, uint32_t b1) {
    asm volatile(
        "mma.sync.aligned.m16n8k16.row.col.f32.f16.f16.f32 "
        "{%0,%1,%2,%3}, {%4,%5,%6,%7}, {%8,%9}, {%0,%1,%2,%3};"
        : "+f"(c[0]), "+f"(c[1]), "+f"(c[2]), "+f"(c[3])
        : "r"(a0), "r"(a1), "r"(a2), "r"(a3), "r"(b0), "r"(b1));
}
#define CP16(dst, src) \
    asm volatile("cp.async.cg.shared.global [%0], [%1], 16;" :: "r"(dst), "l"(src))
#define CP_COMMIT() asm volatile("cp.async.commit_group;")
#define CP_WAIT0()  asm volatile("cp.async.wait_group 0;" ::: "memory")
#define CP_WAIT1()  asm volatile("cp.async.wait_group 1;" ::: "memory")

__device__ __forceinline__ uint4 cfrag_pack(const float* lo, const float* hi) {
    uint4 u;
    u.x = packh2(lo[0], lo[1]);
    u.y = packh2(lo[2], lo[3]);
    u.z = packh2(hi[0], hi[1]);
    u.w = packh2(hi[2], hi[3]);
    return u;
}

// ---------------------------------------------------------------------------
// perm16: fp32 row-major -> fp16 GEMM images, 16-row band per block.
// ---------------------------------------------------------------------------
#define XB  (Mp / 16)        // 520
#define WQB (3072 / 16)      // 192
#define WPB (1024 / 16)      // 64

__global__ void __launch_bounds__(256)
perm16(const float* __restrict__ x, const float* __restrict__ wq,
       const float* __restrict__ wp, uint32_t* __restrict__ xi,
       uint32_t* __restrict__ wqi, uint32_t* __restrict__ wpi)
{
    __shared__ __half s[16][1032];
    const int bid = blockIdx.x;
    const int tid = threadIdx.x;

    const float* src;
    uint32_t* dst;
    int band, rbase;
    bool padded;
    if (bid < XB) {
        band = bid; src = x; dst = xi; padded = true; rbase = 0;
    } else if (bid < XB + WQB) {
        band = bid - XB; src = wq; dst = wqi; padded = false;
        rbase = band * 16;
    } else {
        band = bid - XB - WQB; src = wp; dst = wpi; padded = false;
        rbase = band * 16;
    }

#pragma unroll
    for (int e = 0; e < 32; e++) {
        const int idx = tid + e * 256;
        const int r16 = idx >> 9;
        const int kk = idx & 511;
        float2 v = make_float2(0.f, 0.f);
        if (padded) {
            const int row = band * 16 + r16;
            const int b = row / PadN, n = row - b * PadN;
            if (n < Nn)
                v = *(const float2*)(src + ((size_t)b * Nn + n) * Cn + 2 * kk);
        } else {
            v = *(const float2*)(src + (size_t)(rbase + r16) * Cn + 2 * kk);
        }
        *(__half2*)&s[r16][2 * kk] = __floats2half2_rn(v.x, v.y);
    }
    __syncthreads();

    const int mt = band >> 3, R = band & 7;
#pragma unroll
    for (int e = 0; e < 8; e++) {
        const int f = tid + e * 256;
        const int kc = f >> 7, c8 = (f >> 5) & 3, lane = f & 31;
        const int g2 = lane >> 2, q2 = lane & 3;
        const int col = kc * 64 + c8 * 16 + 2 * q2;
        uint4 u;
        u.x = *(const uint32_t*)&s[g2][col];
        u.y = *(const uint32_t*)&s[g2 + 8][col];
        u.z = *(const uint32_t*)&s[g2][col + 8];
        u.w = *(const uint32_t*)&s[g2 + 8][col + 8];
        *(uint4*)(dst + (size_t)(mt * 16 + kc) * 4096 +
                  ((R * 4 + c8) * 32 + lane) * 4) = u;
    }
}

// ---------------------------------------------------------------------------
// fp16 GEMM (R13 config + y0 tile offset for the split-half launches).
// ---------------------------------------------------------------------------
template <int MODE>
__global__ void __launch_bounds__(256, 2)
gemm_h(const uint32_t* __restrict__ A0img, const uint32_t* __restrict__ A1img,
       const uint32_t* __restrict__ Bimg, const float* __restrict__ bias,
       float* __restrict__ Cout, int y0)
{
    extern __shared__ char smraw[];
    const uint32_t sb = smem_u32(smraw);
    const int tid = threadIdx.x;
    const int w = tid >> 5, l = tid & 31;
    const int q = l & 3, g = l >> 2;
    const int yt = blockIdx.y + y0;
    const int m0 = yt * 128;
    const int n0 = blockIdx.x * 128;
    const int R0  = (w & 3) * 2;
    const int wn2 = w >> 2;

    const uint32_t* Aimg = blockIdx.z ? A1img : A0img;
    if (MODE == 1) Cout += (size_t)blockIdx.z * Mn * Cn;

    const char* Ab = (const char*)(Aimg + (size_t)yt * 16 * 4096);
    const char* Bb = (const char*)(Bimg + (size_t)blockIdx.x * 16 * 4096);

#define GISSUE(kt) do {                                                      \
    const uint32_t st = sb + (uint32_t)((kt) % 3) * 32768u;                  \
    const char* as = Ab + (size_t)(kt) * 16384;                              \
    const char* bs = Bb + (size_t)(kt) * 16384;                              \
    _Pragma("unroll")                                                        \
    for (int i_ = 0; i_ < 4; i_++) {                                         \
        CP16(st + (tid + i_ * 256) * 16,          as + (tid + i_ * 256) * 16); \
        CP16(st + 16384u + (tid + i_ * 256) * 16, bs + (tid + i_ * 256) * 16); \
    }                                                                        \
    CP_COMMIT(); } while (0)

    float acc[2][8][4];
#pragma unroll
    for (int i = 0; i < 2; i++)
#pragma unroll
        for (int j = 0; j < 8; j++)
#pragma unroll
            for (int e = 0; e < 4; e++) acc[i][j][e] = 0.f;

    GISSUE(0);
    GISSUE(1);

    for (int kt = 0; kt < 16; kt++) {
        if (kt < 15) { CP_WAIT1(); } else { CP_WAIT0(); }
        __syncthreads();
        const uint32_t ab = sb + (uint32_t)(kt % 3) * 32768u;
        const uint32_t bb = ab + 16384u;
#pragma unroll
        for (int c8 = 0; c8 < 4; c8++) {
            uint4 af[2], bf[4];
#pragma unroll
            for (int i = 0; i < 2; i++)
                lds128(af[i], ab + (((R0 + i) * 4 + c8) * 32 + l) * 16);
#pragma unroll
            for (int nn = 0; nn < 4; nn++)
                lds128(bf[nn], bb + (((wn2 * 4 + nn) * 4 + c8) * 32 + l) * 16);
#pragma unroll
            for (int i = 0; i < 2; i++)
#pragma unroll
                for (int nn = 0; nn < 4; nn++) {
                    mma16(acc[i][2 * nn],     af[i].x, af[i].y, af[i].z, af[i].w,
                          bf[nn].x, bf[nn].z);
                    mma16(acc[i][2 * nn + 1], af[i].x, af[i].y, af[i].z, af[i].w,
                          bf[nn].y, bf[nn].w);
                }
        }
        if (kt + 2 < 16) GISSUE(kt + 2);
    }
#undef GISSUE

    if (MODE == 0) {
        const int gn_base = n0 + wn2 * 64;
        const int sel = gn_base >> 10;
        const int h   = (gn_base & 1023) >> 6;
        __half* stg = (__half*)(smraw + 32768 + w * 2176);
#pragma unroll
        for (int i = 0; i < 2; i++) {
            const int gmb = m0 + (R0 + i) * 16;
            const int b   = gmb / PadN;
            const int tok = gmb - b * PadN;
            const int bh  = b * Hn + h;
            const int nb16 = tok >> 4;
            const int t    = tok >> 6;
            const int N16  = (tok & 63) >> 4;
            uint32_t* aimg_p = q_aimg + (size_t)bh * 33280;
            uint32_t* kimg_p = ((sel == 1) ? k_kimg : v_kimg) +
                               ((size_t)bh * NT + t) * 2048;
#pragma unroll
            for (int c8 = 0; c8 < 4; c8++) {
                const float* lo = acc[i][2 * c8];
                const float* hi = acc[i][2 * c8 + 1];
                if (sel == 0)
                    *(uint4*)(aimg_p + ((nb16 * 4 + c8) * 32 + l) * 4) =
                        cfrag_pack(lo, hi);
                else
                    *(uint4*)(kimg_p + ((N16 * 4 + c8) * 32 + l) * 4) =
                        cfrag_pack(lo, hi);
            }
            if (sel == 2) {
#pragma unroll
                for (int j = 0; j < 8; j++) {
                    *(__half2*)(stg + g * 66 + 8 * j + 2 * q) =
                        __floats2half2_rn(acc[i][j][0], acc[i][j][1]);
                    *(__half2*)(stg + (g + 8) * 66 + 8 * j + 2 * q) =
                        __floats2half2_rn(acc[i][j][2], acc[i][j][3]);
                }
                __syncwarp();
                uint32_t* vvp = v_vimg + ((size_t)bh * NT + t) * 2048;
#pragma unroll
                for (int b2 = 0; b2 < 4; b2++) {
                    const int d0 = b2 * 16 + g, d1 = d0 + 8;
                    const int kA = 2 * q, kB = 2 * q + 8;
                    uint4 u;
                    u.x = pack2h(stg[kA * 66 + d0], stg[(kA + 1) * 66 + d0]);
                    u.y = pack2h(stg[kA * 66 + d1], stg[(kA + 1) * 66 + d1]);
                    u.z = pack2h(stg[kB * 66 + d0], stg[(kB + 1) * 66 + d0]);
                    u.w = pack2h(stg[kB * 66 + d1], stg[(kB + 1) * 66 + d1]);
                    *(uint4*)(vvp + ((b2 * 4 + N16) * 32 + l) * 4) = u;
                }
                __syncwarp();
            }
        }
    } else {
#pragma unroll
        for (int i = 0; i < 2; i++) {
            const int gmb = m0 + (R0 + i) * 16;
            const int b   = gmb / PadN;
            const int tok0 = gmb - b * PadN + g;
            const int tok1 = tok0 + 8;
            float* r0 = Cout + ((size_t)b * Nn + tok0) * Cn;
            float* r1 = Cout + ((size_t)b * Nn + tok1) * Cn;
            const bool v0 = tok0 < Nn, v1 = tok1 < Nn;
#pragma unroll
            for (int j = 0; j < 8; j++) {
                const int gn = n0 + wn2 * 64 + 8 * j + 2 * q;
                float2 bv = *(const float2*)(bias + gn);
                if (v0)
                    *(float2*)(r0 + gn) = make_float2(acc[i][j][0] + bv.x,
                                                      acc[i][j][1] + bv.y);
                if (v1)
                    *(float2*)(r1 + gn) = make_float2(acc[i][j][2] + bv.x,
                                                      acc[i][j][3] + bv.y);
            }
        }
    }
}

// ---------------------------------------------------------------------------
// Fused fp16 flash attention (R14 form: scalar l-sum on the idle fma pipe,
// one shfl tree at the end — no extra tensor-pipe work).
// ---------------------------------------------------------------------------
__global__ void __launch_bounds__(256, 2)
attn_h(const uint32_t* __restrict__ Qa, const uint32_t* __restrict__ Kk0,
       const uint32_t* __restrict__ Kk1, const uint32_t* __restrict__ Vv,
       uint32_t* __restrict__ X0, uint32_t* __restrict__ X1, int bh0)
{
    extern __shared__ char smraw[];
    const uint32_t sb = smem_u32(smraw);
    const int tid = threadIdx.x;
    const int w = tid >> 5, l = tid & 31;
    const int bh = blockIdx.y + bh0;
    const int b = bh >> 4, h = bh & 15;
    const int z = blockIdx.z;
    const int gr_base = blockIdx.x * 128 + w * 16;
    const int nb  = blockIdx.x * 8 + w;
    const bool act = (gr_base < Nn);
    const float off  = z ? 14.0f : 0.0f;
    const float corr = z ? (63.0f / 16384.0f) : 63.0f;   // 63 * 2^-off

    const uint32_t* Kk = z ? Kk1 : Kk0;
    uint32_t*       Xi = z ? X1 : X0;

    const char* Kb = (const char*)(Kk + (size_t)bh * NT * 2048);
    const char* Vb = (const char*)(Vv + (size_t)bh * NT * 2048);

    uint4 qa[4];
    if (act) {
        const uint32_t* qp;
        int blk4;
        if (z == 0) { qp = Qa + (size_t)bh * 33280;                 blk4 = nb * 4; }
        else        { qp = Kk1 + ((size_t)bh * NT + (nb >> 2)) * 2048;
                      blk4 = (nb & 3) * 4; }
#pragma unroll
        for (int c8 = 0; c8 < 4; c8++)
            qa[c8] = *(const uint4*)(qp + ((blk4 + c8) * 32 + l) * 4);
    } else {
#pragma unroll
        for (int c8 = 0; c8 < 4; c8++) qa[c8] = make_uint4(0, 0, 0, 0);
    }

    float o[8][4];
#pragma unroll
    for (int j = 0; j < 8; j++)
#pragma unroll
        for (int e = 0; e < 4; e++) o[j][e] = 0.f;
    float l0 = 0.f, l1 = 0.f;

#define AISSUE(T) do {                                                       \
    const uint32_t bo = sb + (uint32_t)((T) % 3) * 32768u;                   \
    const char* ks = Kb + (size_t)(T) * 16384;                               \
    const char* vs = Vb + (size_t)(T) * 16384;                               \
    _Pragma("unroll")                                                        \
    for (int i_ = 0; i_ < 4; i_++) {                                         \
        CP16(bo + (tid + i_ * 256) * 16,          ks + (tid + i_ * 256) * 16); \
        CP16(bo + 16384u + (tid + i_ * 256) * 16, vs + (tid + i_ * 256) * 16); \
    }                                                                        \
    CP_COMMIT(); } while (0)

    AISSUE(0);
    AISSUE(1);

    for (int T = 0; T < NT2; T++) {
        if (T < NT2 - 1) { CP_WAIT1(); } else { CP_WAIT0(); }
        __syncthreads();
        const uint32_t stg0 = sb + (uint32_t)(T % 3) * 32768u;

#pragma unroll
        for (int sub = 0; sub < 2; sub++) {
            const int kvbase = T * 128 + sub * 64;
            if (!act || kvbase >= Nn) continue;
            const uint32_t k_s = stg0 + (uint32_t)sub * 8192u;
            const uint32_t v_s = stg0 + 16384u + (uint32_t)sub * 8192u;

            float sa[8][4];
#pragma unroll
            for (int j = 0; j < 8; j++)
#pragma unroll
                for (int e = 0; e < 4; e++) sa[j][e] = 0.f;
#pragma unroll
            for (int c8 = 0; c8 < 4; c8++) {
#pragma unroll
                for (int n16 = 0; n16 < 4; n16++) {
                    uint4 bf;
                    lds128(bf, k_s + ((n16 * 4 + c8) * 32 + l) * 16);
                    mma16(sa[2 * n16],     qa[c8].x, qa[c8].y, qa[c8].z,
                          qa[c8].w, bf.x, bf.z);
                    mma16(sa[2 * n16 + 1], qa[c8].x, qa[c8].y, qa[c8].z,
                          qa[c8].w, bf.y, bf.w);
                }
            }

            // P = 2^(s*SCL - off); scalar row-sum accumulation (fma pipe)
#pragma unroll
            for (int j = 0; j < 8; j++) {
                sa[j][0] = ex2f(sa[j][0] * SCL - off);
                sa[j][1] = ex2f(sa[j][1] * SCL - off);
                sa[j][2] = ex2f(sa[j][2] * SCL - off);
                sa[j][3] = ex2f(sa[j][3] * SCL - off);
                l0 += sa[j][0] + sa[j][1];
                l1 += sa[j][2] + sa[j][3];
            }

            // O += P @ V  (P C-frags pack straight into A-frags)
#pragma unroll
            for (int c = 0; c < 4; c++) {
                const uint32_t a0 = packh2(sa[2 * c][0],     sa[2 * c][1]);
                const uint32_t a1 = packh2(sa[2 * c][2],     sa[2 * c][3]);
                const uint32_t a2 = packh2(sa[2 * c + 1][0], sa[2 * c + 1][1]);
                const uint32_t a3 = packh2(sa[2 * c + 1][2], sa[2 * c + 1][3]);
#pragma unroll
                for (int n16 = 0; n16 < 4; n16++) {
                    uint4 vf;
                    lds128(vf, v_s + ((n16 * 4 + c) * 32 + l) * 16);
                    mma16(o[2 * n16],     a0, a1, a2, a3, vf.x, vf.z);
                    mma16(o[2 * n16 + 1], a0, a1, a2, a3, vf.y, vf.w);
                }
            }
        }

        if (T + 2 < NT2) AISSUE(T + 2);
    }
#undef AISSUE

    if (act) {
        l0 += __shfl_xor_sync(0xffffffffu, l0, 1);
        l0 += __shfl_xor_sync(0xffffffffu, l0, 2);
        l1 += __shfl_xor_sync(0xffffffffu, l1, 1);
        l1 += __shfl_xor_sync(0xffffffffu, l1, 2);
        const float inv0 = 1.0f / (l0 - corr);
        const float inv1 = 1.0f / (l1 - corr);

        const int m_base = b * PadN + gr_base;
        const int mt = m_base >> 7, R = (m_base & 127) >> 4;
        uint32_t* tb = Xi + (size_t)(mt * 16 + h) * 4096;
#pragma unroll
        for (int c8 = 0; c8 < 4; c8++) {
            uint4 u;
            u.x = packh2(o[2 * c8][0] * inv0,     o[2 * c8][1] * inv0);
            u.y = packh2(o[2 * c8][2] * inv1,     o[2 * c8][3] * inv1);
            u.z = packh2(o[2 * c8 + 1][0] * inv0, o[2 * c8 + 1][1] * inv0);
            u.w = packh2(o[2 * c8 + 1][2] * inv1, o[2 * c8 + 1][3] * inv1);
            *(uint4*)(tb + ((R * 4 + c8) * 32 + l) * 4) = u;
        }
    }
}

// ---------------------------------------------------------------------------
// Launch: two independent stream lanes with tile-32 duplication.
//   s0: g0a (tiles 0-32)  -> attnA (bh<64)  -> projA (tiles 0-31)
//   s1: g0b (tiles 32-64) -> attnB (bh>=64) -> projB (tiles 32-64, waits attnA)
// Tile 32 computed on BOTH streams (identical values; benign duplicate stores)
// so neither attention half waits on the other stream's gemm0.
// ---------------------------------------------------------------------------
extern "C" void kernel_launch(void* const* d_in, const int* in_sizes, int n_in,
                              void* d_out, int out_size)
{
    const float* x      = (const float*)d_in[0];
    const float* w_qkv  = (const float*)d_in[1];
    const float* w_proj = (const float*)d_in[2];
    const float* b_proj = (const float*)d_in[3];
    float*       out    = (float*)d_out;

    uint32_t *xi, *wqi, *wpi, *xoi, *xni, *qai, *kki, *vki, *vvi;
    cudaGetSymbolAddress((void**)&xi,  x_img);
    cudaGetSymbolAddress((void**)&wqi, wq_img);
    cudaGetSymbolAddress((void**)&wpi, wp_img);
    cudaGetSymbolAddress((void**)&xoi, xo_img);
    cudaGetSymbolAddress((void**)&xni, xn_img);
    cudaGetSymbolAddress((void**)&qai, q_aimg);
    cudaGetSymbolAddress((void**)&kki, k_kimg);
    cudaGetSymbolAddress((void**)&vki, v_kimg);
    cudaGetSymbolAddress((void**)&vvi, v_vimg);

    const int smem_gemm = 98304;
    const int smem_attn = 98304;
    cudaFuncSetAttribute(gemm_h<0>, cudaFuncAttributeMaxDynamicSharedMemorySize,
                         smem_gemm);
    cudaFuncSetAttribute(gemm_h<1>, cudaFuncAttributeMaxDynamicSharedMemorySize,
                         smem_gemm);
    cudaFuncSetAttribute(attn_h, cudaFuncAttributeMaxDynamicSharedMemorySize,
                         smem_attn);

    static cudaStream_t s1 = nullptr;
    static cudaEvent_t evPerm, evAttnA, evEnd;
    if (s1 == nullptr) {
        cudaStreamCreateWithFlags(&s1, cudaStreamNonBlocking);
        cudaEventCreateWithFlags(&evPerm,  cudaEventDisableTiming);
        cudaEventCreateWithFlags(&evAttnA, cudaEventDisableTiming);
        cudaEventCreateWithFlags(&evEnd,   cudaEventDisableTiming);
    }

    // 0) images
    perm16<<<XB + WQB + WPB, 256>>>(x, w_qkv, w_proj, xi, wqi, wpi);
    cudaEventRecord(evPerm, 0);
    cudaStreamWaitEvent(s1, evPerm, 0);

    // 1) QKV projection, split by row tiles (tile 32 duplicated on both)
    gemm_h<0><<<dim3(24, 33, 1), 256, smem_gemm, s1>>>(xi, xi, wqi, nullptr,
                                                       nullptr, 32);  // g0b
    gemm_h<0><<<dim3(24, 33, 1), 256, smem_gemm>>>(xi, xi, wqi, nullptr,
                                                   nullptr, 0);       // g0a

    // 2) attention: each half depends only on its own stream's gemm0
    attn_h<<<dim3(9, 64, 2), 256, smem_attn>>>(qai, kki, vki, vvi,
                                               xoi, xni, 0);          // attnA
    cudaEventRecord(evAttnA, 0);
    attn_h<<<dim3(9, 64, 2), 256, smem_attn, s1>>>(qai, kki, vki, vvi,
                                                   xoi, xni, 64);     // attnB

    // 3) projections: projA (s0) after attnA; projB (s1) needs attnA too
    gemm_h<1><<<dim3(8, 32, 2), 256, smem_gemm>>>(xni, xoi, wpi, b_proj,
                                                  out, 0);            // projA
    cudaStreamWaitEvent(s1, evAttnA, 0);
    gemm_h<1><<<dim3(8, 33, 2), 256, smem_gemm, s1>>>(xni, xoi, wpi, b_proj,
                                                      out, 32);       // projB

    // join
    cudaEventRecord(evEnd, s1);
    cudaStreamWaitEvent(0, evEnd, 0);
}